// round 15
// baseline (speedup 1.0000x reference)
#include <cuda_runtime.h>
#include <cuda_fp16.h>
#include <cstdint>
#include <cstddef>

#define S_LEN 2048
#define HID   2048
#define NH    16
#define HD    128
#define BATCH 2
#define MROWS (BATCH * S_LEN)

// ---------------------------------------------------------------------------
// Scratch (allocation-free rule: device globals)
// ---------------------------------------------------------------------------
__device__ __half g_xh [(size_t)MROWS * HID];
__device__ __half g_wh [4][(size_t)HID * HID];
__device__ __half g_qh [(size_t)MROWS * HID];
__device__ __half g_kh [(size_t)MROWS * HID];
__device__ __half g_vh [(size_t)MROWS * HID];
__device__ __half g_aoh[(size_t)MROWS * HID];

// ---------------------------------------------------------------------------
// helpers
// ---------------------------------------------------------------------------
__device__ __forceinline__ uint32_t smem_u32(const void* p) {
  uint32_t a;
  asm("{ .reg .u64 t; cvta.to.shared.u64 t, %1; cvt.u32.u64 %0, t; }"
      : "=r"(a) : "l"(p));
  return a;
}

__device__ __forceinline__ void ldsm4(uint32_t addr, uint32_t& r0, uint32_t& r1,
                                      uint32_t& r2, uint32_t& r3) {
  asm volatile("ldmatrix.sync.aligned.m8n8.x4.shared.b16 {%0,%1,%2,%3}, [%4];"
               : "=r"(r0), "=r"(r1), "=r"(r2), "=r"(r3) : "r"(addr));
}

__device__ __forceinline__ void ldsm4t(uint32_t addr, uint32_t& r0, uint32_t& r1,
                                       uint32_t& r2, uint32_t& r3) {
  asm volatile("ldmatrix.sync.aligned.m8n8.x4.trans.shared.b16 {%0,%1,%2,%3}, [%4];"
               : "=r"(r0), "=r"(r1), "=r"(r2), "=r"(r3) : "r"(addr));
}

__device__ __forceinline__ void mma16816h(float* d, const uint32_t* a,
                                          const uint32_t* b) {
  asm volatile(
      "mma.sync.aligned.m16n8k16.row.col.f32.f16.f16.f32 "
      "{%0,%1,%2,%3}, {%4,%5,%6,%7}, {%8,%9}, {%0,%1,%2,%3};"
      : "+f"(d[0]), "+f"(d[1]), "+f"(d[2]), "+f"(d[3])
      : "r"(a[0]), "r"(a[1]), "r"(a[2]), "r"(a[3]), "r"(b[0]), "r"(b[1]));
}

#define CP_ASYNC16(saddr, gaddr) \
  asm volatile("cp.async.cg.shared.global [%0], [%1], 16;" \
               :: "r"(saddr), "l"(gaddr))
#define CP_COMMIT() asm volatile("cp.async.commit_group;")
#define CP_WAIT1()  asm volatile("cp.async.wait_group 1;")
#define CP_WAIT0()  asm volatile("cp.async.wait_group 0;")

// FFMA-only exp2 (no MUFU): magic-round + degree-6 Taylor, |err| < 2e-7.
__device__ __forceinline__ float exp2p(float x) {
  x = fmaxf(x, -126.f);
  float r = x + 12582912.f;
  int   e = __float_as_int(r) - 0x4B400000;
  float f = x - (r - 12582912.f);
  float p = 1.5403e-4f;
  p = fmaf(p, f, 1.3333558e-3f);
  p = fmaf(p, f, 9.6181291e-3f);
  p = fmaf(p, f, 5.5504109e-2f);
  p = fmaf(p, f, 2.4022651e-1f);
  p = fmaf(p, f, 6.9314718e-1f);
  p = fmaf(p, f, 1.0f);
  return __int_as_float(__float_as_int(p) + (e << 23));
}

__device__ __forceinline__ uint32_t pack_h(float x, float y) {
  __half2 t = __floats2half2_rn(x, y);
  return *(uint32_t*)&t;
}

// ---------------------------------------------------------------------------
// fp32 -> fp16 convert pass
// ---------------------------------------------------------------------------
__global__ void cvt_h(const float* __restrict__ in, __half* __restrict__ out,
                      int n) {
  int i = (blockIdx.x * blockDim.x + threadIdx.x) * 8;
  if (i >= n) return;
  float4 a = *(const float4*)(in + i);
  float4 b = *(const float4*)(in + i + 4);
  uint4 o;
  o.x = pack_h(a.x, a.y);
  o.y = pack_h(a.z, a.w);
  o.z = pack_h(b.x, b.y);
  o.w = pack_h(b.z, b.w);
  *(uint4*)(out + i) = o;
}

// ---------------------------------------------------------------------------
// fp16 HMMA GEMM (round-13 proven): out = A @ W^T (+bias).
// Writes fp32 (final output) or fp16 (intermediates).
// ---------------------------------------------------------------------------
#define BKH 32
#define NCHH (HID / BKH)
#define TSTRH 40
#define TELEMH (128 * TSTRH)
#define GEMM_H_SMEM (2 * 2 * TELEMH * 2)

__global__ __launch_bounds__(256, 2) void gemm_h(
    const __half* __restrict__ A, const __half* __restrict__ W,
    const float* __restrict__ bias, float* __restrict__ C,
    __half* __restrict__ hO) {
  extern __shared__ __half smh[];
  const uint32_t sbase = smem_u32(smh);
  const int tid  = threadIdx.x;
  const int wid  = tid >> 5;
  const int lane = tid & 31;
  const int bm = blockIdx.y << 7;
  const int bn = blockIdx.x << 7;
  const int warp_m = (wid & 1) << 6;
  const int warp_n = (wid >> 1) << 5;

  const __half* gp[2] = {A + (size_t)bm * HID, W + (size_t)bn * HID};

  auto issue_chunk = [&](int c) {
    const int p = c & 1;
    const int k0 = c * BKH;
    const uint32_t s0 = sbase + p * 2 * TELEMH * 2;
#pragma unroll
    for (int t = 0; t < 2; t++) {
#pragma unroll
      for (int i = 0; i < 2; i++) {
        int u = tid + (i << 8);
        int row = u >> 2;
        int cc = (u & 3) << 3;
        const __half* ga = gp[t] + (size_t)row * HID + k0 + cc;
        uint32_t sa = s0 + (t * TELEMH + row * TSTRH + cc) * 2;
        CP_ASYNC16(sa, ga);
      }
    }
    CP_COMMIT();
  };

  float acc[4][4][4];
#pragma unroll
  for (int mt = 0; mt < 4; mt++)
#pragma unroll
    for (int nt = 0; nt < 4; nt++)
#pragma unroll
      for (int r = 0; r < 4; r++) acc[mt][nt][r] = 0.f;

  issue_chunk(0);

  for (int c = 0; c < NCHH; c++) {
    if (c + 1 < NCHH) { issue_chunk(c + 1); CP_WAIT1(); }
    else              { CP_WAIT0(); }
    __syncthreads();

    const uint32_t buf = sbase + (c & 1) * 2 * TELEMH * 2;
    const uint32_t sA = buf;
    const uint32_t sB = buf + TELEMH * 2;

#pragma unroll
    for (int ks = 0; ks < 2; ks++) {
      const int kc = ks << 4;
      uint32_t a[4][4];
      const int arow = warp_m + (lane & 15);
      const int acol = kc + ((lane >> 4) << 3);
#pragma unroll
      for (int mt = 0; mt < 4; mt++) {
        uint32_t off = ((arow + (mt << 4)) * TSTRH + acol) * 2;
        ldsm4(sA + off, a[mt][0], a[mt][1], a[mt][2], a[mt][3]);
      }
      uint32_t b[4][2];
      const int brow0 = (lane & 7) + ((lane >> 4) << 3);
      const int bcol  = kc + (((lane >> 3) & 1) << 3);
#pragma unroll
      for (int pr = 0; pr < 2; pr++) {
        const int nb = warp_n + (pr << 4);
        uint32_t off = ((nb + brow0) * TSTRH + bcol) * 2;
        ldsm4(sB + off, b[pr*2][0], b[pr*2][1], b[pr*2+1][0], b[pr*2+1][1]);
      }
#pragma unroll
      for (int mt = 0; mt < 4; mt++)
#pragma unroll
        for (int nt = 0; nt < 4; nt++)
          mma16816h(acc[mt][nt], a[mt], b[nt]);
    }
    __syncthreads();
  }

  const int r  = lane >> 2;
  const int c2 = (lane & 3) << 1;
#pragma unroll
  for (int mt = 0; mt < 4; mt++) {
    const int row0 = bm + warp_m + (mt << 4) + r;
#pragma unroll
    for (int nt = 0; nt < 4; nt++) {
      const int col = bn + warp_n + (nt << 3) + c2;
      float b0 = 0.f, b1 = 0.f;
      if (bias) { b0 = bias[col]; b1 = bias[col + 1]; }
      float v00 = acc[mt][nt][0] + b0, v01 = acc[mt][nt][1] + b1;
      float v10 = acc[mt][nt][2] + b0, v11 = acc[mt][nt][3] + b1;
      if (hO) {
        *(uint32_t*)&hO[(size_t)row0 * HID + col]       = pack_h(v00, v01);
        *(uint32_t*)&hO[(size_t)(row0 + 8) * HID + col] = pack_h(v10, v11);
      } else {
        float2 o0 = {v00, v01};
        float2 o1 = {v10, v11};
        *(float2*)&C[(size_t)row0 * HID + col]       = o0;
        *(float2*)&C[(size_t)(row0 + 8) * HID + col] = o1;
      }
    }
  }
}

// ---------------------------------------------------------------------------
// RoPE in place on fp16 q/k. q gets scale*log2(e) folded in.
// Each thread owns the (d, d+64) pair exclusively -> in-place is race-free.
// ---------------------------------------------------------------------------
__global__ void rope_h(__half* __restrict__ qh, __half* __restrict__ kh,
                       const float* __restrict__ cosb,
                       const float* __restrict__ sinb)
{
  const float SC = 0.08838834764831845f * 1.4426950408889634f;
  int i = blockIdx.x * blockDim.x + threadIdx.x;
  int d  = i & 63;
  int h  = (i >> 6) & 15;
  int ms = i >> 10;
  int s  = ms & (S_LEN - 1);
  size_t base = (size_t)ms * HID + (size_t)h * HD;

  float c1 = cosb[s * HD + d],      s1 = sinb[s * HD + d];
  float c2 = cosb[s * HD + d + 64], s2 = sinb[s * HD + d + 64];

  float q1 = __half2float(qh[base + d]), q2 = __half2float(qh[base + d + 64]);
  float k1 = __half2float(kh[base + d]), k2 = __half2float(kh[base + d + 64]);
  qh[base + d]      = __float2half_rn((q1 * c1 - q2 * s1) * SC);
  qh[base + d + 64] = __float2half_rn((q2 * c2 + q1 * s2) * SC);
  kh[base + d]      = __float2half_rn(k1 * c1 - k2 * s1);
  kh[base + d + 64] = __float2half_rn(k2 * c2 + k1 * s2);
}

// ---------------------------------------------------------------------------
// Flash attention, all-fp16 MMA, exp2 softmax, 64-row kv tiles — now at
// 3 CTAs/SM (3 warps/SMSP): the kernel measures 3x above its smem/MMA
// floors, i.e. latency-bound; +50% resident warps attacks exactly that.
// ---------------------------------------------------------------------------
#define KSTR 136
#define Q_ROWS 64
#define KV_ROWS 64
#define KH_BYTES (KV_ROWS * KSTR * 2)          // 17408
#define STAGE_BYTES (2 * KH_BYTES)             // K + V = 34816
#define A_SMEM (2 * STAGE_BYTES)               // 69632

__global__ __launch_bounds__(128, 3) void attn_h(
    const __half* __restrict__ qh, const __half* __restrict__ kh,
    const __half* __restrict__ vh, __half* __restrict__ O)
{
  extern __shared__ char sma[];
  const uint32_t sb = smem_u32(sma);
  const int tid  = threadIdx.x;
  const int wid  = tid >> 5;
  const int lane = tid & 31;
  const int q0 = blockIdx.x << 6;
  const int b  = blockIdx.y >> 4;
  const int h  = blockIdx.y & 15;
  const int warp_m = wid << 4;

  const size_t bS = (size_t)b * S_LEN;
  const size_t h128 = (size_t)h * HD;

  auto issue_kv = [&](int t) {
    const uint32_t stb = sb + (uint32_t)(t & 1) * STAGE_BYTES;
    const int kv0 = t << 6;
#pragma unroll
    for (int i = 0; i < 8; i++) {
      int u = tid + (i << 7);
      int row = u >> 4, c8 = (u & 15) << 3;
      size_t g = (bS + kv0 + row) * HID + h128 + c8;
      uint32_t so = (uint32_t)(row * KSTR + c8) * 2;
      CP_ASYNC16(stb + so,            kh + g);
      CP_ASYNC16(stb + KH_BYTES + so, vh + g);
    }
    CP_COMMIT();
  };
  issue_kv(0);
  issue_kv(1);

  // ---- Q fp16 fragments via direct LDG (m16n8k16 A-frag layout)
  uint32_t aQ[8][4];
  {
    const int r0 = warp_m + (lane >> 2);
    const int c0 = (lane & 3) << 1;
    const __half* gq = qh + (bS + q0 + r0) * HID + h128 + c0;
#pragma unroll
    for (int ks = 0; ks < 8; ks++) {
      const __half* p = gq + (ks << 4);
      aQ[ks][0] = *(const uint32_t*)(p);
      aQ[ks][1] = *(const uint32_t*)(p + 8 * HID);
      aQ[ks][2] = *(const uint32_t*)(p + 8);
      aQ[ks][3] = *(const uint32_t*)(p + 8 * HID + 8);
    }
  }

  float m0 = -1e30f, m1 = -1e30f, l0 = 0.f, l1 = 0.f;
  float Oa[16][4];
#pragma unroll
  for (int j = 0; j < 16; j++)
#pragma unroll
    for (int r = 0; r < 4; r++) Oa[j][r] = 0.f;

  const int NT = S_LEN / KV_ROWS;   // 32
  for (int t = 0; t < NT; t++) {
    if (t < NT - 1) CP_WAIT1(); else CP_WAIT0();
    __syncthreads();

    const uint32_t stb = sb + (uint32_t)(t & 1) * STAGE_BYTES;
    const uint32_t sK = stb;
    const uint32_t sV = stb + KH_BYTES;

    // ---- QK(t): 16 x 64 scores
    float S[8][4];
#pragma unroll
    for (int j = 0; j < 8; j++)
#pragma unroll
      for (int r = 0; r < 4; r++) S[j][r] = 0.f;

#pragma unroll
    for (int kc = 0; kc < 8; kc++) {
#pragma unroll
      for (int np = 0; np < 4; np++) {
        uint32_t bK[4];
        const uint32_t koff =
            (uint32_t)(((np << 4) + (lane & 7) + (((lane >> 4) & 1) << 3)) * KSTR
                       + (kc << 4) + (((lane >> 3) & 1) << 3)) * 2;
        ldsm4(sK + koff, bK[0], bK[1], bK[2], bK[3]);
        mma16816h(S[np * 2],     aQ[kc], bK);
        mma16816h(S[np * 2 + 1], aQ[kc], bK + 2);
      }
    }

    // ---- softmax(t) (exp2 domain)
    float mx0 = m0, mx1 = m1;
#pragma unroll
    for (int j = 0; j < 8; j++) {
      mx0 = fmaxf(mx0, fmaxf(S[j][0], S[j][1]));
      mx1 = fmaxf(mx1, fmaxf(S[j][2], S[j][3]));
    }
    mx0 = fmaxf(mx0, __shfl_xor_sync(0xffffffffu, mx0, 1));
    mx0 = fmaxf(mx0, __shfl_xor_sync(0xffffffffu, mx0, 2));
    mx1 = fmaxf(mx1, __shfl_xor_sync(0xffffffffu, mx1, 1));
    mx1 = fmaxf(mx1, __shfl_xor_sync(0xffffffffu, mx1, 2));
    const float al0 = exp2p(m0 - mx0);
    const float al1 = exp2p(m1 - mx1);
    m0 = mx0; m1 = mx1;

    uint32_t ph[8][2];
    float sum0 = 0.f, sum1 = 0.f;
#pragma unroll
    for (int j = 0; j < 8; j++) {
      float p00 = exp2p(S[j][0] - mx0);
      float p01 = exp2p(S[j][1] - mx0);
      float p10 = exp2p(S[j][2] - mx1);
      float p11 = exp2p(S[j][3] - mx1);
      sum0 += p00 + p01;
      sum1 += p10 + p11;
      ph[j][0] = pack_h(p00, p01);
      ph[j][1] = pack_h(p10, p11);
    }
    l0 = l0 * al0 + sum0;
    l1 = l1 * al1 + sum1;
#pragma unroll
    for (int j = 0; j < 16; j++) {
      Oa[j][0] *= al0; Oa[j][1] *= al0;
      Oa[j][2] *= al1; Oa[j][3] *= al1;
    }

    // ---- PV(t): fp16 single pass over 64 kv rows
#pragma unroll
    for (int kk = 0; kk < 4; kk++) {
      uint32_t paH[4] = {ph[kk*2][0], ph[kk*2][1], ph[kk*2+1][0], ph[kk*2+1][1]};
#pragma unroll
      for (int dp = 0; dp < 8; dp++) {
        uint32_t bV[4];
        const uint32_t voff =
            (uint32_t)(((kk << 4) + (lane & 7) + (((lane >> 3) & 1) << 3)) * KSTR
                       + (dp << 4) + ((lane >> 4) << 3)) * 2;
        ldsm4t(sV + voff, bV[0], bV[1], bV[2], bV[3]);
        mma16816h(Oa[dp * 2],     paH, bV);
        mma16816h(Oa[dp * 2 + 1], paH, bV + 2);
      }
    }

    __syncthreads();
    if (t + 2 < NT) issue_kv(t + 2);
  }

  // ---- epilogue (fp16 out)
  l0 += __shfl_xor_sync(0xffffffffu, l0, 1);
  l0 += __shfl_xor_sync(0xffffffffu, l0, 2);
  l1 += __shfl_xor_sync(0xffffffffu, l1, 1);
  l1 += __shfl_xor_sync(0xffffffffu, l1, 2);
  const float inv0 = 1.f / l0;
  const float inv1 = 1.f / l1;
  const int row0 = q0 + warp_m + (lane >> 2);
  const int cofs = (lane & 3) << 1;
#pragma unroll
  for (int j = 0; j < 16; j++) {
    const int col = (j << 3) + cofs;
    *(uint32_t*)&O[(bS + row0) * HID + h128 + col] =
        pack_h(Oa[j][0] * inv0, Oa[j][1] * inv0);
    *(uint32_t*)&O[(bS + row0 + 8) * HID + h128 + col] =
        pack_h(Oa[j][2] * inv1, Oa[j][3] * inv1);
  }
}

// ---------------------------------------------------------------------------
extern "C" void kernel_launch(void* const* d_in, const int* in_sizes, int n_in,
                              void* d_out, int out_size)
{
  (void)in_sizes; (void)n_in; (void)out_size;
  const float* x    = (const float*)d_in[0];
  const float* cosb = (const float*)d_in[1];
  const float* sinb = (const float*)d_in[2];
  const float* wq   = (const float*)d_in[3];
  const float* bq   = (const float*)d_in[4];
  const float* wk   = (const float*)d_in[5];
  const float* bk   = (const float*)d_in[6];
  const float* wv   = (const float*)d_in[7];
  const float* bv   = (const float*)d_in[8];
  const float* wo   = (const float*)d_in[9];
  float* out = (float*)d_out;

  __half *xh, *wh, *qh, *kh, *vh, *aoh;
  cudaGetSymbolAddress((void**)&xh,  g_xh);
  cudaGetSymbolAddress((void**)&wh,  g_wh);
  cudaGetSymbolAddress((void**)&qh,  g_qh);
  cudaGetSymbolAddress((void**)&kh,  g_kh);
  cudaGetSymbolAddress((void**)&vh,  g_vh);
  cudaGetSymbolAddress((void**)&aoh, g_aoh);

  static bool attrs_set = false;
  if (!attrs_set) {
    cudaFuncSetAttribute(gemm_h,
                         cudaFuncAttributeMaxDynamicSharedMemorySize, GEMM_H_SMEM);
    cudaFuncSetAttribute(attn_h,
                         cudaFuncAttributeMaxDynamicSharedMemorySize, A_SMEM);
    attrs_set = true;
  }

  const int NX = MROWS * HID;
  const int NW = HID * HID;
  const size_t WS = (size_t)HID * HID;

  cvt_h<<<NX / 2048, 256>>>(x,  xh, NX);
  cvt_h<<<NW / 2048, 256>>>(wq, wh + 0 * WS, NW);
  cvt_h<<<NW / 2048, 256>>>(wk, wh + 1 * WS, NW);
  cvt_h<<<NW / 2048, 256>>>(wv, wh + 2 * WS, NW);
  cvt_h<<<NW / 2048, 256>>>(wo, wh + 3 * WS, NW);

  dim3 gg(HID / 128, MROWS / 128);  // (16, 32)
  gemm_h<<<gg, 256, GEMM_H_SMEM>>>(xh, wh + 0 * WS, bq, nullptr, qh);
  gemm_h<<<gg, 256, GEMM_H_SMEM>>>(xh, wh + 1 * WS, bk, nullptr, kh);
  gemm_h<<<gg, 256, GEMM_H_SMEM>>>(xh, wh + 2 * WS, bv, nullptr, vh);

  rope_h<<<(MROWS * NH * 64) / 256, 256>>>(qh, kh, cosb, sinb);

  attn_h<<<dim3(S_LEN / Q_ROWS, BATCH * NH), 128, A_SMEM>>>(qh, kh, vh, aoh);

  gemm_h<<<gg, 256, GEMM_H_SMEM>>>(aoh, wh + 3 * WS, nullptr, out, nullptr);
}

// round 16
// speedup vs baseline: 1.0375x; 1.0375x over previous
#include <cuda_runtime.h>
#include <cuda_fp16.h>
#include <cstdint>
#include <cstddef>

#define S_LEN 2048
#define HID   2048
#define NH    16
#define HD    128
#define BATCH 2
#define MROWS (BATCH * S_LEN)

// ---------------------------------------------------------------------------
// Scratch (allocation-free rule: device globals)
// ---------------------------------------------------------------------------
__device__ __half g_xh [(size_t)MROWS * HID];
__device__ __half g_wh [4][(size_t)HID * HID];
__device__ __half g_qh [(size_t)MROWS * HID];
__device__ __half g_kh [(size_t)MROWS * HID];
__device__ __half g_vh [(size_t)MROWS * HID];
__device__ __half g_aoh[(size_t)MROWS * HID];

// ---------------------------------------------------------------------------
// helpers
// ---------------------------------------------------------------------------
__device__ __forceinline__ uint32_t smem_u32(const void* p) {
  uint32_t a;
  asm("{ .reg .u64 t; cvta.to.shared.u64 t, %1; cvt.u32.u64 %0, t; }"
      : "=r"(a) : "l"(p));
  return a;
}

__device__ __forceinline__ void ldsm4(uint32_t addr, uint32_t& r0, uint32_t& r1,
                                      uint32_t& r2, uint32_t& r3) {
  asm volatile("ldmatrix.sync.aligned.m8n8.x4.shared.b16 {%0,%1,%2,%3}, [%4];"
               : "=r"(r0), "=r"(r1), "=r"(r2), "=r"(r3) : "r"(addr));
}

__device__ __forceinline__ void ldsm4t(uint32_t addr, uint32_t& r0, uint32_t& r1,
                                       uint32_t& r2, uint32_t& r3) {
  asm volatile("ldmatrix.sync.aligned.m8n8.x4.trans.shared.b16 {%0,%1,%2,%3}, [%4];"
               : "=r"(r0), "=r"(r1), "=r"(r2), "=r"(r3) : "r"(addr));
}

__device__ __forceinline__ void mma16816h(float* d, const uint32_t* a,
                                          const uint32_t* b) {
  asm volatile(
      "mma.sync.aligned.m16n8k16.row.col.f32.f16.f16.f32 "
      "{%0,%1,%2,%3}, {%4,%5,%6,%7}, {%8,%9}, {%0,%1,%2,%3};"
      : "+f"(d[0]), "+f"(d[1]), "+f"(d[2]), "+f"(d[3])
      : "r"(a[0]), "r"(a[1]), "r"(a[2]), "r"(a[3]), "r"(b[0]), "r"(b[1]));
}

#define CP_ASYNC16(saddr, gaddr) \
  asm volatile("cp.async.cg.shared.global [%0], [%1], 16;" \
               :: "r"(saddr), "l"(gaddr))
#define CP_COMMIT() asm volatile("cp.async.commit_group;")
#define CP_WAIT1()  asm volatile("cp.async.wait_group 1;")
#define CP_WAIT0()  asm volatile("cp.async.wait_group 0;")

// FFMA-only exp2 (no MUFU): magic-round + degree-6 Taylor, |err| < 2e-7.
__device__ __forceinline__ float exp2p(float x) {
  x = fmaxf(x, -126.f);
  float r = x + 12582912.f;
  int   e = __float_as_int(r) - 0x4B400000;
  float f = x - (r - 12582912.f);
  float p = 1.5403e-4f;
  p = fmaf(p, f, 1.3333558e-3f);
  p = fmaf(p, f, 9.6181291e-3f);
  p = fmaf(p, f, 5.5504109e-2f);
  p = fmaf(p, f, 2.4022651e-1f);
  p = fmaf(p, f, 6.9314718e-1f);
  p = fmaf(p, f, 1.0f);
  return __int_as_float(__float_as_int(p) + (e << 23));
}

__device__ __forceinline__ uint32_t pack_h(float x, float y) {
  __half2 t = __floats2half2_rn(x, y);
  return *(uint32_t*)&t;
}

// ---------------------------------------------------------------------------
// fp32 -> fp16 convert passes
// ---------------------------------------------------------------------------
__global__ void cvt_h(const float* __restrict__ in, __half* __restrict__ out,
                      int n) {
  int i = (blockIdx.x * blockDim.x + threadIdx.x) * 8;
  if (i >= n) return;
  float4 a = *(const float4*)(in + i);
  float4 b = *(const float4*)(in + i + 4);
  uint4 o;
  o.x = pack_h(a.x, a.y);
  o.y = pack_h(a.z, a.w);
  o.z = pack_h(b.x, b.y);
  o.w = pack_h(b.z, b.w);
  *(uint4*)(out + i) = o;
}

// all 4 weight matrices in one launch (better fill than 4 tiny grids)
__global__ void cvt_w4(const float* __restrict__ w0, const float* __restrict__ w1,
                       const float* __restrict__ w2, const float* __restrict__ w3,
                       __half* __restrict__ out) {
  const int NW = HID * HID;
  int g = (blockIdx.x * blockDim.x + threadIdx.x) * 8;   // over 4*NW
  int seg = g / NW;
  int i = g - seg * NW;
  const float* in = (seg == 0) ? w0 : (seg == 1) ? w1 : (seg == 2) ? w2 : w3;
  float4 a = *(const float4*)(in + i);
  float4 b = *(const float4*)(in + i + 4);
  uint4 o;
  o.x = pack_h(a.x, a.y);
  o.y = pack_h(a.z, a.w);
  o.z = pack_h(b.x, b.y);
  o.w = pack_h(b.z, b.w);
  *(uint4*)(out + (size_t)seg * NW + i) = o;
}

// ---------------------------------------------------------------------------
// fp16 HMMA GEMM (round-13 proven): out = A @ W^T (+bias).
// Writes fp32 (final output) or fp16 (intermediates).
// ---------------------------------------------------------------------------
#define BKH 32
#define NCHH (HID / BKH)
#define TSTRH 40
#define TELEMH (128 * TSTRH)
#define GEMM_H_SMEM (2 * 2 * TELEMH * 2)

__global__ __launch_bounds__(256, 2) void gemm_h(
    const __half* __restrict__ A, const __half* __restrict__ W,
    const float* __restrict__ bias, float* __restrict__ C,
    __half* __restrict__ hO) {
  extern __shared__ __half smh[];
  const uint32_t sbase = smem_u32(smh);
  const int tid  = threadIdx.x;
  const int wid  = tid >> 5;
  const int lane = tid & 31;
  const int bm = blockIdx.y << 7;
  const int bn = blockIdx.x << 7;
  const int warp_m = (wid & 1) << 6;
  const int warp_n = (wid >> 1) << 5;

  const __half* gp[2] = {A + (size_t)bm * HID, W + (size_t)bn * HID};

  auto issue_chunk = [&](int c) {
    const int p = c & 1;
    const int k0 = c * BKH;
    const uint32_t s0 = sbase + p * 2 * TELEMH * 2;
#pragma unroll
    for (int t = 0; t < 2; t++) {
#pragma unroll
      for (int i = 0; i < 2; i++) {
        int u = tid + (i << 8);
        int row = u >> 2;
        int cc = (u & 3) << 3;
        const __half* ga = gp[t] + (size_t)row * HID + k0 + cc;
        uint32_t sa = s0 + (t * TELEMH + row * TSTRH + cc) * 2;
        CP_ASYNC16(sa, ga);
      }
    }
    CP_COMMIT();
  };

  float acc[4][4][4];
#pragma unroll
  for (int mt = 0; mt < 4; mt++)
#pragma unroll
    for (int nt = 0; nt < 4; nt++)
#pragma unroll
      for (int r = 0; r < 4; r++) acc[mt][nt][r] = 0.f;

  issue_chunk(0);

  for (int c = 0; c < NCHH; c++) {
    if (c + 1 < NCHH) { issue_chunk(c + 1); CP_WAIT1(); }
    else              { CP_WAIT0(); }
    __syncthreads();

    const uint32_t buf = sbase + (c & 1) * 2 * TELEMH * 2;
    const uint32_t sA = buf;
    const uint32_t sB = buf + TELEMH * 2;

#pragma unroll
    for (int ks = 0; ks < 2; ks++) {
      const int kc = ks << 4;
      uint32_t a[4][4];
      const int arow = warp_m + (lane & 15);
      const int acol = kc + ((lane >> 4) << 3);
#pragma unroll
      for (int mt = 0; mt < 4; mt++) {
        uint32_t off = ((arow + (mt << 4)) * TSTRH + acol) * 2;
        ldsm4(sA + off, a[mt][0], a[mt][1], a[mt][2], a[mt][3]);
      }
      uint32_t b[4][2];
      const int brow0 = (lane & 7) + ((lane >> 4) << 3);
      const int bcol  = kc + (((lane >> 3) & 1) << 3);
#pragma unroll
      for (int pr = 0; pr < 2; pr++) {
        const int nb = warp_n + (pr << 4);
        uint32_t off = ((nb + brow0) * TSTRH + bcol) * 2;
        ldsm4(sB + off, b[pr*2][0], b[pr*2][1], b[pr*2+1][0], b[pr*2+1][1]);
      }
#pragma unroll
      for (int mt = 0; mt < 4; mt++)
#pragma unroll
        for (int nt = 0; nt < 4; nt++)
          mma16816h(acc[mt][nt], a[mt], b[nt]);
    }
    __syncthreads();
  }

  const int r  = lane >> 2;
  const int c2 = (lane & 3) << 1;
#pragma unroll
  for (int mt = 0; mt < 4; mt++) {
    const int row0 = bm + warp_m + (mt << 4) + r;
#pragma unroll
    for (int nt = 0; nt < 4; nt++) {
      const int col = bn + warp_n + (nt << 3) + c2;
      float b0 = 0.f, b1 = 0.f;
      if (bias) { b0 = bias[col]; b1 = bias[col + 1]; }
      float v00 = acc[mt][nt][0] + b0, v01 = acc[mt][nt][1] + b1;
      float v10 = acc[mt][nt][2] + b0, v11 = acc[mt][nt][3] + b1;
      if (hO) {
        *(uint32_t*)&hO[(size_t)row0 * HID + col]       = pack_h(v00, v01);
        *(uint32_t*)&hO[(size_t)(row0 + 8) * HID + col] = pack_h(v10, v11);
      } else {
        float2 o0 = {v00, v01};
        float2 o1 = {v10, v11};
        *(float2*)&C[(size_t)row0 * HID + col]       = o0;
        *(float2*)&C[(size_t)(row0 + 8) * HID + col] = o1;
      }
    }
  }
}

// ---------------------------------------------------------------------------
// RoPE in place on fp16 q/k. q gets scale*log2(e) folded in.
// Each thread owns the (d, d+64) pair exclusively -> in-place is race-free.
// ---------------------------------------------------------------------------
__global__ void rope_h(__half* __restrict__ qh, __half* __restrict__ kh,
                       const float* __restrict__ cosb,
                       const float* __restrict__ sinb)
{
  const float SC = 0.08838834764831845f * 1.4426950408889634f;
  int i = blockIdx.x * blockDim.x + threadIdx.x;
  int d  = i & 63;
  int h  = (i >> 6) & 15;
  int ms = i >> 10;
  int s  = ms & (S_LEN - 1);
  size_t base = (size_t)ms * HID + (size_t)h * HD;

  float c1 = cosb[s * HD + d],      s1 = sinb[s * HD + d];
  float c2 = cosb[s * HD + d + 64], s2 = sinb[s * HD + d + 64];

  float q1 = __half2float(qh[base + d]), q2 = __half2float(qh[base + d + 64]);
  float k1 = __half2float(kh[base + d]), k2 = __half2float(kh[base + d + 64]);
  qh[base + d]      = __float2half_rn((q1 * c1 - q2 * s1) * SC);
  qh[base + d + 64] = __float2half_rn((q2 * c2 + q1 * s2) * SC);
  kh[base + d]      = __float2half_rn(k1 * c1 - k2 * s1);
  kh[base + d + 64] = __float2half_rn(k2 * c2 + k1 * s2);
}

// ---------------------------------------------------------------------------
// Flash attention, all-fp16 MMA, exp2 softmax, 64-row kv tiles.
// launch_bounds(128, 2): 256-reg cap — NO spills (the (128,3) variant
// spilled at its 170-reg cap and regressed; occupancy beyond 2 CTAs/SM
// requires a register diet, not a flag).
// ---------------------------------------------------------------------------
#define KSTR 136
#define Q_ROWS 64
#define KV_ROWS 64
#define KH_BYTES (KV_ROWS * KSTR * 2)          // 17408
#define STAGE_BYTES (2 * KH_BYTES)             // K + V = 34816
#define A_SMEM (2 * STAGE_BYTES)               // 69632

__global__ __launch_bounds__(128, 2) void attn_h(
    const __half* __restrict__ qh, const __half* __restrict__ kh,
    const __half* __restrict__ vh, __half* __restrict__ O)
{
  extern __shared__ char sma[];
  const uint32_t sb = smem_u32(sma);
  const int tid  = threadIdx.x;
  const int wid  = tid >> 5;
  const int lane = tid & 31;
  const int q0 = blockIdx.x << 6;
  const int b  = blockIdx.y >> 4;
  const int h  = blockIdx.y & 15;
  const int warp_m = wid << 4;

  const size_t bS = (size_t)b * S_LEN;
  const size_t h128 = (size_t)h * HD;

  auto issue_kv = [&](int t) {
    const uint32_t stb = sb + (uint32_t)(t & 1) * STAGE_BYTES;
    const int kv0 = t << 6;
#pragma unroll
    for (int i = 0; i < 8; i++) {
      int u = tid + (i << 7);
      int row = u >> 4, c8 = (u & 15) << 3;
      size_t g = (bS + kv0 + row) * HID + h128 + c8;
      uint32_t so = (uint32_t)(row * KSTR + c8) * 2;
      CP_ASYNC16(stb + so,            kh + g);
      CP_ASYNC16(stb + KH_BYTES + so, vh + g);
    }
    CP_COMMIT();
  };
  issue_kv(0);
  issue_kv(1);

  // ---- Q fp16 fragments via direct LDG (m16n8k16 A-frag layout)
  uint32_t aQ[8][4];
  {
    const int r0 = warp_m + (lane >> 2);
    const int c0 = (lane & 3) << 1;
    const __half* gq = qh + (bS + q0 + r0) * HID + h128 + c0;
#pragma unroll
    for (int ks = 0; ks < 8; ks++) {
      const __half* p = gq + (ks << 4);
      aQ[ks][0] = *(const uint32_t*)(p);
      aQ[ks][1] = *(const uint32_t*)(p + 8 * HID);
      aQ[ks][2] = *(const uint32_t*)(p + 8);
      aQ[ks][3] = *(const uint32_t*)(p + 8 * HID + 8);
    }
  }

  float m0 = -1e30f, m1 = -1e30f, l0 = 0.f, l1 = 0.f;
  float Oa[16][4];
#pragma unroll
  for (int j = 0; j < 16; j++)
#pragma unroll
    for (int r = 0; r < 4; r++) Oa[j][r] = 0.f;

  const int NT = S_LEN / KV_ROWS;   // 32
  for (int t = 0; t < NT; t++) {
    if (t < NT - 1) CP_WAIT1(); else CP_WAIT0();
    __syncthreads();

    const uint32_t stb = sb + (uint32_t)(t & 1) * STAGE_BYTES;
    const uint32_t sK = stb;
    const uint32_t sV = stb + KH_BYTES;

    // ---- QK(t): 16 x 64 scores
    float S[8][4];
#pragma unroll
    for (int j = 0; j < 8; j++)
#pragma unroll
      for (int r = 0; r < 4; r++) S[j][r] = 0.f;

#pragma unroll
    for (int kc = 0; kc < 8; kc++) {
#pragma unroll
      for (int np = 0; np < 4; np++) {
        uint32_t bK[4];
        const uint32_t koff =
            (uint32_t)(((np << 4) + (lane & 7) + (((lane >> 4) & 1) << 3)) * KSTR
                       + (kc << 4) + (((lane >> 3) & 1) << 3)) * 2;
        ldsm4(sK + koff, bK[0], bK[1], bK[2], bK[3]);
        mma16816h(S[np * 2],     aQ[kc], bK);
        mma16816h(S[np * 2 + 1], aQ[kc], bK + 2);
      }
    }

    // ---- softmax(t) (exp2 domain)
    float mx0 = m0, mx1 = m1;
#pragma unroll
    for (int j = 0; j < 8; j++) {
      mx0 = fmaxf(mx0, fmaxf(S[j][0], S[j][1]));
      mx1 = fmaxf(mx1, fmaxf(S[j][2], S[j][3]));
    }
    mx0 = fmaxf(mx0, __shfl_xor_sync(0xffffffffu, mx0, 1));
    mx0 = fmaxf(mx0, __shfl_xor_sync(0xffffffffu, mx0, 2));
    mx1 = fmaxf(mx1, __shfl_xor_sync(0xffffffffu, mx1, 1));
    mx1 = fmaxf(mx1, __shfl_xor_sync(0xffffffffu, mx1, 2));
    const float al0 = exp2p(m0 - mx0);
    const float al1 = exp2p(m1 - mx1);
    m0 = mx0; m1 = mx1;

    uint32_t ph[8][2];
    float sum0 = 0.f, sum1 = 0.f;
#pragma unroll
    for (int j = 0; j < 8; j++) {
      float p00 = exp2p(S[j][0] - mx0);
      float p01 = exp2p(S[j][1] - mx0);
      float p10 = exp2p(S[j][2] - mx1);
      float p11 = exp2p(S[j][3] - mx1);
      sum0 += p00 + p01;
      sum1 += p10 + p11;
      ph[j][0] = pack_h(p00, p01);
      ph[j][1] = pack_h(p10, p11);
    }
    l0 = l0 * al0 + sum0;
    l1 = l1 * al1 + sum1;
#pragma unroll
    for (int j = 0; j < 16; j++) {
      Oa[j][0] *= al0; Oa[j][1] *= al0;
      Oa[j][2] *= al1; Oa[j][3] *= al1;
    }

    // ---- PV(t): fp16 single pass over 64 kv rows
#pragma unroll
    for (int kk = 0; kk < 4; kk++) {
      uint32_t paH[4] = {ph[kk*2][0], ph[kk*2][1], ph[kk*2+1][0], ph[kk*2+1][1]};
#pragma unroll
      for (int dp = 0; dp < 8; dp++) {
        uint32_t bV[4];
        const uint32_t voff =
            (uint32_t)(((kk << 4) + (lane & 7) + (((lane >> 3) & 1) << 3)) * KSTR
                       + (dp << 4) + ((lane >> 4) << 3)) * 2;
        ldsm4t(sV + voff, bV[0], bV[1], bV[2], bV[3]);
        mma16816h(Oa[dp * 2],     paH, bV);
        mma16816h(Oa[dp * 2 + 1], paH, bV + 2);
      }
    }

    __syncthreads();
    if (t + 2 < NT) issue_kv(t + 2);
  }

  // ---- epilogue (fp16 out)
  l0 += __shfl_xor_sync(0xffffffffu, l0, 1);
  l0 += __shfl_xor_sync(0xffffffffu, l0, 2);
  l1 += __shfl_xor_sync(0xffffffffu, l1, 1);
  l1 += __shfl_xor_sync(0xffffffffu, l1, 2);
  const float inv0 = 1.f / l0;
  const float inv1 = 1.f / l1;
  const int row0 = q0 + warp_m + (lane >> 2);
  const int cofs = (lane & 3) << 1;
#pragma unroll
  for (int j = 0; j < 16; j++) {
    const int col = (j << 3) + cofs;
    *(uint32_t*)&O[(bS + row0) * HID + h128 + col] =
        pack_h(Oa[j][0] * inv0, Oa[j][1] * inv0);
    *(uint32_t*)&O[(bS + row0 + 8) * HID + h128 + col] =
        pack_h(Oa[j][2] * inv1, Oa[j][3] * inv1);
  }
}

// ---------------------------------------------------------------------------
extern "C" void kernel_launch(void* const* d_in, const int* in_sizes, int n_in,
                              void* d_out, int out_size)
{
  (void)in_sizes; (void)n_in; (void)out_size;
  const float* x    = (const float*)d_in[0];
  const float* cosb = (const float*)d_in[1];
  const float* sinb = (const float*)d_in[2];
  const float* wq   = (const float*)d_in[3];
  const float* bq   = (const float*)d_in[4];
  const float* wk   = (const float*)d_in[5];
  const float* bk   = (const float*)d_in[6];
  const float* wv   = (const float*)d_in[7];
  const float* bv   = (const float*)d_in[8];
  const float* wo   = (const float*)d_in[9];
  float* out = (float*)d_out;

  __half *xh, *wh, *qh, *kh, *vh, *aoh;
  cudaGetSymbolAddress((void**)&xh,  g_xh);
  cudaGetSymbolAddress((void**)&wh,  g_wh);
  cudaGetSymbolAddress((void**)&qh,  g_qh);
  cudaGetSymbolAddress((void**)&kh,  g_kh);
  cudaGetSymbolAddress((void**)&vh,  g_vh);
  cudaGetSymbolAddress((void**)&aoh, g_aoh);

  static bool attrs_set = false;
  if (!attrs_set) {
    cudaFuncSetAttribute(gemm_h,
                         cudaFuncAttributeMaxDynamicSharedMemorySize, GEMM_H_SMEM);
    cudaFuncSetAttribute(attn_h,
                         cudaFuncAttributeMaxDynamicSharedMemorySize, A_SMEM);
    attrs_set = true;
  }

  const int NX = MROWS * HID;
  const int NW = HID * HID;
  const size_t WS = (size_t)HID * HID;

  cvt_h<<<NX / 2048, 256>>>(x, xh, NX);
  cvt_w4<<<(4 * NW) / 2048, 256>>>(wq, wk, wv, wo, wh);

  dim3 gg(HID / 128, MROWS / 128);  // (16, 32)
  gemm_h<<<gg, 256, GEMM_H_SMEM>>>(xh, wh + 0 * WS, bq, nullptr, qh);
  gemm_h<<<gg, 256, GEMM_H_SMEM>>>(xh, wh + 1 * WS, bk, nullptr, kh);
  gemm_h<<<gg, 256, GEMM_H_SMEM>>>(xh, wh + 2 * WS, bv, nullptr, vh);

  rope_h<<<(MROWS * NH * 64) / 256, 256>>>(qh, kh, cosb, sinb);

  attn_h<<<dim3(S_LEN / Q_ROWS, BATCH * NH), 128, A_SMEM>>>(qh, kh, vh, aoh);

  gemm_h<<<gg, 256, GEMM_H_SMEM>>>(aoh, wh + 3 * WS, nullptr, out, nullptr);
}

// round 17
// speedup vs baseline: 1.0851x; 1.0459x over previous
#include <cuda_runtime.h>
#include <cuda_fp16.h>
#include <cstdint>
#include <cstddef>

#define S_LEN 2048
#define HID   2048
#define NH    16
#define HD    128
#define BATCH 2
#define MROWS (BATCH * S_LEN)

// ---------------------------------------------------------------------------
// Scratch (allocation-free rule: device globals)
// ---------------------------------------------------------------------------
__device__ __half g_xh [(size_t)MROWS * HID];
__device__ __half g_wh [4][(size_t)HID * HID];
__device__ __half g_qh [(size_t)MROWS * HID];
__device__ __half g_kh [(size_t)MROWS * HID];
__device__ __half g_vh [(size_t)MROWS * HID];
__device__ __half g_aoh[(size_t)MROWS * HID];

// ---------------------------------------------------------------------------
// helpers
// ---------------------------------------------------------------------------
__device__ __forceinline__ uint32_t smem_u32(const void* p) {
  uint32_t a;
  asm("{ .reg .u64 t; cvta.to.shared.u64 t, %1; cvt.u32.u64 %0, t; }"
      : "=r"(a) : "l"(p));
  return a;
}

__device__ __forceinline__ void ldsm4(uint32_t addr, uint32_t& r0, uint32_t& r1,
                                      uint32_t& r2, uint32_t& r3) {
  asm volatile("ldmatrix.sync.aligned.m8n8.x4.shared.b16 {%0,%1,%2,%3}, [%4];"
               : "=r"(r0), "=r"(r1), "=r"(r2), "=r"(r3) : "r"(addr));
}

__device__ __forceinline__ void ldsm4t(uint32_t addr, uint32_t& r0, uint32_t& r1,
                                       uint32_t& r2, uint32_t& r3) {
  asm volatile("ldmatrix.sync.aligned.m8n8.x4.trans.shared.b16 {%0,%1,%2,%3}, [%4];"
               : "=r"(r0), "=r"(r1), "=r"(r2), "=r"(r3) : "r"(addr));
}

__device__ __forceinline__ void mma16816h(float* d, const uint32_t* a,
                                          const uint32_t* b) {
  asm volatile(
      "mma.sync.aligned.m16n8k16.row.col.f32.f16.f16.f32 "
      "{%0,%1,%2,%3}, {%4,%5,%6,%7}, {%8,%9}, {%0,%1,%2,%3};"
      : "+f"(d[0]), "+f"(d[1]), "+f"(d[2]), "+f"(d[3])
      : "r"(a[0]), "r"(a[1]), "r"(a[2]), "r"(a[3]), "r"(b[0]), "r"(b[1]));
}

#define CP_ASYNC16(saddr, gaddr) \
  asm volatile("cp.async.cg.shared.global [%0], [%1], 16;" \
               :: "r"(saddr), "l"(gaddr))
#define CP_COMMIT() asm volatile("cp.async.commit_group;")
#define CP_WAIT2()  asm volatile("cp.async.wait_group 2;")
#define CP_WAIT1()  asm volatile("cp.async.wait_group 1;")
#define CP_WAIT0()  asm volatile("cp.async.wait_group 0;")

// FFMA-only exp2 (no MUFU): magic-round + degree-6 Taylor, |err| < 2e-7.
__device__ __forceinline__ float exp2p(float x) {
  x = fmaxf(x, -126.f);
  float r = x + 12582912.f;
  int   e = __float_as_int(r) - 0x4B400000;
  float f = x - (r - 12582912.f);
  float p = 1.5403e-4f;
  p = fmaf(p, f, 1.3333558e-3f);
  p = fmaf(p, f, 9.6181291e-3f);
  p = fmaf(p, f, 5.5504109e-2f);
  p = fmaf(p, f, 2.4022651e-1f);
  p = fmaf(p, f, 6.9314718e-1f);
  p = fmaf(p, f, 1.0f);
  return __int_as_float(__float_as_int(p) + (e << 23));
}

__device__ __forceinline__ uint32_t pack_h(float x, float y) {
  __half2 t = __floats2half2_rn(x, y);
  return *(uint32_t*)&t;
}

// ---------------------------------------------------------------------------
// fp32 -> fp16 convert passes
// ---------------------------------------------------------------------------
__global__ void cvt_h(const float* __restrict__ in, __half* __restrict__ out,
                      int n) {
  int i = (blockIdx.x * blockDim.x + threadIdx.x) * 8;
  if (i >= n) return;
  float4 a = *(const float4*)(in + i);
  float4 b = *(const float4*)(in + i + 4);
  uint4 o;
  o.x = pack_h(a.x, a.y);
  o.y = pack_h(a.z, a.w);
  o.z = pack_h(b.x, b.y);
  o.w = pack_h(b.z, b.w);
  *(uint4*)(out + i) = o;
}

__global__ void cvt_w4(const float* __restrict__ w0, const float* __restrict__ w1,
                       const float* __restrict__ w2, const float* __restrict__ w3,
                       __half* __restrict__ out) {
  const int NW = HID * HID;
  int g = (blockIdx.x * blockDim.x + threadIdx.x) * 8;
  int seg = g / NW;
  int i = g - seg * NW;
  const float* in = (seg == 0) ? w0 : (seg == 1) ? w1 : (seg == 2) ? w2 : w3;
  float4 a = *(const float4*)(in + i);
  float4 b = *(const float4*)(in + i + 4);
  uint4 o;
  o.x = pack_h(a.x, a.y);
  o.y = pack_h(a.z, a.w);
  o.z = pack_h(b.x, b.y);
  o.w = pack_h(b.z, b.w);
  *(uint4*)(out + (size_t)seg * NW + i) = o;
}

// ---------------------------------------------------------------------------
// fp16 HMMA GEMM, 4-stage cp.async ring, ONE barrier per chunk.
// ncu showed tensor=41.8%, occ=22%, DRAM=2.3%: latency-bound with a
// 2-stage pipeline. 4 stages give each load ~3 chunk-times; the trailing
// barrier is removed (write slot (c+3)&3 == (c-1)&3, finished by all
// warps before the iter-c barrier).
// ---------------------------------------------------------------------------
#define BKH 32
#define NCHH (HID / BKH)          // 64
#define TSTRH 40
#define TELEMH (128 * TSTRH)      // 5120 elems/tile
#define NSTG 4
#define STG_ELEM (2 * TELEMH)     // A+B per stage
#define GEMM_H_SMEM (NSTG * STG_ELEM * 2)   // 81920 bytes

__global__ __launch_bounds__(256, 2) void gemm_h(
    const __half* __restrict__ A, const __half* __restrict__ W,
    const float* __restrict__ bias, float* __restrict__ C,
    __half* __restrict__ hO) {
  extern __shared__ __half smh[];
  const uint32_t sbase = smem_u32(smh);
  const int tid  = threadIdx.x;
  const int wid  = tid >> 5;
  const int lane = tid & 31;
  const int bm = blockIdx.y << 7;
  const int bn = blockIdx.x << 7;
  const int warp_m = (wid & 1) << 6;
  const int warp_n = (wid >> 1) << 5;

  const __half* gp[2] = {A + (size_t)bm * HID, W + (size_t)bn * HID};

  auto issue_chunk = [&](int c) {
    const int slot = c & (NSTG - 1);
    const int k0 = c * BKH;
    const uint32_t s0 = sbase + slot * STG_ELEM * 2;
#pragma unroll
    for (int t = 0; t < 2; t++) {
#pragma unroll
      for (int i = 0; i < 2; i++) {
        int u = tid + (i << 8);
        int row = u >> 2;
        int cc = (u & 3) << 3;
        const __half* ga = gp[t] + (size_t)row * HID + k0 + cc;
        uint32_t sa = s0 + (t * TELEMH + row * TSTRH + cc) * 2;
        CP_ASYNC16(sa, ga);
      }
    }
    CP_COMMIT();
  };

  float acc[4][4][4];
#pragma unroll
  for (int mt = 0; mt < 4; mt++)
#pragma unroll
    for (int nt = 0; nt < 4; nt++)
#pragma unroll
      for (int r = 0; r < 4; r++) acc[mt][nt][r] = 0.f;

  issue_chunk(0);
  issue_chunk(1);
  issue_chunk(2);

  for (int c = 0; c < NCHH; c++) {
    if (c <= NCHH - 3)      CP_WAIT2();
    else if (c == NCHH - 2) CP_WAIT1();
    else                    CP_WAIT0();
    __syncthreads();
    if (c + 3 < NCHH) issue_chunk(c + 3);

    const uint32_t buf = sbase + (uint32_t)(c & (NSTG - 1)) * STG_ELEM * 2;
    const uint32_t sA = buf;
    const uint32_t sB = buf + TELEMH * 2;

#pragma unroll
    for (int ks = 0; ks < 2; ks++) {
      const int kc = ks << 4;
      uint32_t a[4][4];
      const int arow = warp_m + (lane & 15);
      const int acol = kc + ((lane >> 4) << 3);
#pragma unroll
      for (int mt = 0; mt < 4; mt++) {
        uint32_t off = ((arow + (mt << 4)) * TSTRH + acol) * 2;
        ldsm4(sA + off, a[mt][0], a[mt][1], a[mt][2], a[mt][3]);
      }
      uint32_t b[4][2];
      const int brow0 = (lane & 7) + ((lane >> 4) << 3);
      const int bcol  = kc + (((lane >> 3) & 1) << 3);
#pragma unroll
      for (int pr = 0; pr < 2; pr++) {
        const int nb = warp_n + (pr << 4);
        uint32_t off = ((nb + brow0) * TSTRH + bcol) * 2;
        ldsm4(sB + off, b[pr*2][0], b[pr*2][1], b[pr*2+1][0], b[pr*2+1][1]);
      }
#pragma unroll
      for (int mt = 0; mt < 4; mt++)
#pragma unroll
        for (int nt = 0; nt < 4; nt++)
          mma16816h(acc[mt][nt], a[mt], b[nt]);
    }
  }

  const int r  = lane >> 2;
  const int c2 = (lane & 3) << 1;
#pragma unroll
  for (int mt = 0; mt < 4; mt++) {
    const int row0 = bm + warp_m + (mt << 4) + r;
#pragma unroll
    for (int nt = 0; nt < 4; nt++) {
      const int col = bn + warp_n + (nt << 3) + c2;
      float b0 = 0.f, b1 = 0.f;
      if (bias) { b0 = bias[col]; b1 = bias[col + 1]; }
      float v00 = acc[mt][nt][0] + b0, v01 = acc[mt][nt][1] + b1;
      float v10 = acc[mt][nt][2] + b0, v11 = acc[mt][nt][3] + b1;
      if (hO) {
        *(uint32_t*)&hO[(size_t)row0 * HID + col]       = pack_h(v00, v01);
        *(uint32_t*)&hO[(size_t)(row0 + 8) * HID + col] = pack_h(v10, v11);
      } else {
        float2 o0 = {v00, v01};
        float2 o1 = {v10, v11};
        *(float2*)&C[(size_t)row0 * HID + col]       = o0;
        *(float2*)&C[(size_t)(row0 + 8) * HID + col] = o1;
      }
    }
  }
}

// ---------------------------------------------------------------------------
// RoPE in place on fp16 q/k. q gets scale*log2(e) folded in.
// ---------------------------------------------------------------------------
__global__ void rope_h(__half* __restrict__ qh, __half* __restrict__ kh,
                       const float* __restrict__ cosb,
                       const float* __restrict__ sinb)
{
  const float SC = 0.08838834764831845f * 1.4426950408889634f;
  int i = blockIdx.x * blockDim.x + threadIdx.x;
  int d  = i & 63;
  int h  = (i >> 6) & 15;
  int ms = i >> 10;
  int s  = ms & (S_LEN - 1);
  size_t base = (size_t)ms * HID + (size_t)h * HD;

  float c1 = cosb[s * HD + d],      s1 = sinb[s * HD + d];
  float c2 = cosb[s * HD + d + 64], s2 = sinb[s * HD + d + 64];

  float q1 = __half2float(qh[base + d]), q2 = __half2float(qh[base + d + 64]);
  float k1 = __half2float(kh[base + d]), k2 = __half2float(kh[base + d + 64]);
  qh[base + d]      = __float2half_rn((q1 * c1 - q2 * s1) * SC);
  qh[base + d + 64] = __float2half_rn((q2 * c2 + q1 * s2) * SC);
  kh[base + d]      = __float2half_rn(k1 * c1 - k2 * s1);
  kh[base + d + 64] = __float2half_rn(k2 * c2 + k1 * s2);
}

// ---------------------------------------------------------------------------
// Flash attention, all-fp16 MMA, exp2 softmax, 64-row kv tiles (R14 proven).
// ---------------------------------------------------------------------------
#define KSTR 136
#define Q_ROWS 64
#define KV_ROWS 64
#define KH_BYTES (KV_ROWS * KSTR * 2)
#define STAGE_BYTES (2 * KH_BYTES)
#define A_SMEM (2 * STAGE_BYTES)               // 69632

__global__ __launch_bounds__(128, 2) void attn_h(
    const __half* __restrict__ qh, const __half* __restrict__ kh,
    const __half* __restrict__ vh, __half* __restrict__ O)
{
  extern __shared__ char sma[];
  const uint32_t sb = smem_u32(sma);
  const int tid  = threadIdx.x;
  const int wid  = tid >> 5;
  const int lane = tid & 31;
  const int q0 = blockIdx.x << 6;
  const int b  = blockIdx.y >> 4;
  const int h  = blockIdx.y & 15;
  const int warp_m = wid << 4;

  const size_t bS = (size_t)b * S_LEN;
  const size_t h128 = (size_t)h * HD;

  auto issue_kv = [&](int t) {
    const uint32_t stb = sb + (uint32_t)(t & 1) * STAGE_BYTES;
    const int kv0 = t << 6;
#pragma unroll
    for (int i = 0; i < 8; i++) {
      int u = tid + (i << 7);
      int row = u >> 4, c8 = (u & 15) << 3;
      size_t g = (bS + kv0 + row) * HID + h128 + c8;
      uint32_t so = (uint32_t)(row * KSTR + c8) * 2;
      CP_ASYNC16(stb + so,            kh + g);
      CP_ASYNC16(stb + KH_BYTES + so, vh + g);
    }
    CP_COMMIT();
  };
  issue_kv(0);
  issue_kv(1);

  uint32_t aQ[8][4];
  {
    const int r0 = warp_m + (lane >> 2);
    const int c0 = (lane & 3) << 1;
    const __half* gq = qh + (bS + q0 + r0) * HID + h128 + c0;
#pragma unroll
    for (int ks = 0; ks < 8; ks++) {
      const __half* p = gq + (ks << 4);
      aQ[ks][0] = *(const uint32_t*)(p);
      aQ[ks][1] = *(const uint32_t*)(p + 8 * HID);
      aQ[ks][2] = *(const uint32_t*)(p + 8);
      aQ[ks][3] = *(const uint32_t*)(p + 8 * HID + 8);
    }
  }

  float m0 = -1e30f, m1 = -1e30f, l0 = 0.f, l1 = 0.f;
  float Oa[16][4];
#pragma unroll
  for (int j = 0; j < 16; j++)
#pragma unroll
    for (int r = 0; r < 4; r++) Oa[j][r] = 0.f;

  const int NT = S_LEN / KV_ROWS;   // 32
  for (int t = 0; t < NT; t++) {
    if (t < NT - 1) CP_WAIT1(); else CP_WAIT0();
    __syncthreads();

    const uint32_t stb = sb + (uint32_t)(t & 1) * STAGE_BYTES;
    const uint32_t sK = stb;
    const uint32_t sV = stb + KH_BYTES;

    float S[8][4];
#pragma unroll
    for (int j = 0; j < 8; j++)
#pragma unroll
      for (int r = 0; r < 4; r++) S[j][r] = 0.f;

#pragma unroll
    for (int kc = 0; kc < 8; kc++) {
#pragma unroll
      for (int np = 0; np < 4; np++) {
        uint32_t bK[4];
        const uint32_t koff =
            (uint32_t)(((np << 4) + (lane & 7) + (((lane >> 4) & 1) << 3)) * KSTR
                       + (kc << 4) + (((lane >> 3) & 1) << 3)) * 2;
        ldsm4(sK + koff, bK[0], bK[1], bK[2], bK[3]);
        mma16816h(S[np * 2],     aQ[kc], bK);
        mma16816h(S[np * 2 + 1], aQ[kc], bK + 2);
      }
    }

    float mx0 = m0, mx1 = m1;
#pragma unroll
    for (int j = 0; j < 8; j++) {
      mx0 = fmaxf(mx0, fmaxf(S[j][0], S[j][1]));
      mx1 = fmaxf(mx1, fmaxf(S[j][2], S[j][3]));
    }
    mx0 = fmaxf(mx0, __shfl_xor_sync(0xffffffffu, mx0, 1));
    mx0 = fmaxf(mx0, __shfl_xor_sync(0xffffffffu, mx0, 2));
    mx1 = fmaxf(mx1, __shfl_xor_sync(0xffffffffu, mx1, 1));
    mx1 = fmaxf(mx1, __shfl_xor_sync(0xffffffffu, mx1, 2));
    const float al0 = exp2p(m0 - mx0);
    const float al1 = exp2p(m1 - mx1);
    m0 = mx0; m1 = mx1;

    uint32_t ph[8][2];
    float sum0 = 0.f, sum1 = 0.f;
#pragma unroll
    for (int j = 0; j < 8; j++) {
      float p00 = exp2p(S[j][0] - mx0);
      float p01 = exp2p(S[j][1] - mx0);
      float p10 = exp2p(S[j][2] - mx1);
      float p11 = exp2p(S[j][3] - mx1);
      sum0 += p00 + p01;
      sum1 += p10 + p11;
      ph[j][0] = pack_h(p00, p01);
      ph[j][1] = pack_h(p10, p11);
    }
    l0 = l0 * al0 + sum0;
    l1 = l1 * al1 + sum1;
#pragma unroll
    for (int j = 0; j < 16; j++) {
      Oa[j][0] *= al0; Oa[j][1] *= al0;
      Oa[j][2] *= al1; Oa[j][3] *= al1;
    }

#pragma unroll
    for (int kk = 0; kk < 4; kk++) {
      uint32_t paH[4] = {ph[kk*2][0], ph[kk*2][1], ph[kk*2+1][0], ph[kk*2+1][1]};
#pragma unroll
      for (int dp = 0; dp < 8; dp++) {
        uint32_t bV[4];
        const uint32_t voff =
            (uint32_t)(((kk << 4) + (lane & 7) + (((lane >> 3) & 1) << 3)) * KSTR
                       + (dp << 4) + ((lane >> 4) << 3)) * 2;
        ldsm4t(sV + voff, bV[0], bV[1], bV[2], bV[3]);
        mma16816h(Oa[dp * 2],     paH, bV);
        mma16816h(Oa[dp * 2 + 1], paH, bV + 2);
      }
    }

    __syncthreads();
    if (t + 2 < NT) issue_kv(t + 2);
  }

  l0 += __shfl_xor_sync(0xffffffffu, l0, 1);
  l0 += __shfl_xor_sync(0xffffffffu, l0, 2);
  l1 += __shfl_xor_sync(0xffffffffu, l1, 1);
  l1 += __shfl_xor_sync(0xffffffffu, l1, 2);
  const float inv0 = 1.f / l0;
  const float inv1 = 1.f / l1;
  const int row0 = q0 + warp_m + (lane >> 2);
  const int cofs = (lane & 3) << 1;
#pragma unroll
  for (int j = 0; j < 16; j++) {
    const int col = (j << 3) + cofs;
    *(uint32_t*)&O[(bS + row0) * HID + h128 + col] =
        pack_h(Oa[j][0] * inv0, Oa[j][1] * inv0);
    *(uint32_t*)&O[(bS + row0 + 8) * HID + h128 + col] =
        pack_h(Oa[j][2] * inv1, Oa[j][3] * inv1);
  }
}

// ---------------------------------------------------------------------------
extern "C" void kernel_launch(void* const* d_in, const int* in_sizes, int n_in,
                              void* d_out, int out_size)
{
  (void)in_sizes; (void)n_in; (void)out_size;
  const float* x    = (const float*)d_in[0];
  const float* cosb = (const float*)d_in[1];
  const float* sinb = (const float*)d_in[2];
  const float* wq   = (const float*)d_in[3];
  const float* bq   = (const float*)d_in[4];
  const float* wk   = (const float*)d_in[5];
  const float* bk   = (const float*)d_in[6];
  const float* wv   = (const float*)d_in[7];
  const float* bv   = (const float*)d_in[8];
  const float* wo   = (const float*)d_in[9];
  float* out = (float*)d_out;

  __half *xh, *wh, *qh, *kh, *vh, *aoh;
  cudaGetSymbolAddress((void**)&xh,  g_xh);
  cudaGetSymbolAddress((void**)&wh,  g_wh);
  cudaGetSymbolAddress((void**)&qh,  g_qh);
  cudaGetSymbolAddress((void**)&kh,  g_kh);
  cudaGetSymbolAddress((void**)&vh,  g_vh);
  cudaGetSymbolAddress((void**)&aoh, g_aoh);

  static bool attrs_set = false;
  if (!attrs_set) {
    cudaFuncSetAttribute(gemm_h,
                         cudaFuncAttributeMaxDynamicSharedMemorySize, GEMM_H_SMEM);
    cudaFuncSetAttribute(attn_h,
                         cudaFuncAttributeMaxDynamicSharedMemorySize, A_SMEM);
    attrs_set = true;
  }

  const int NX = MROWS * HID;
  const int NW = HID * HID;
  const size_t WS = (size_t)HID * HID;

  cvt_h<<<NX / 2048, 256>>>(x, xh, NX);
  cvt_w4<<<(4 * NW) / 2048, 256>>>(wq, wk, wv, wo, wh);

  dim3 gg(HID / 128, MROWS / 128);  // (16, 32)
  gemm_h<<<gg, 256, GEMM_H_SMEM>>>(xh, wh + 0 * WS, bq, nullptr, qh);
  gemm_h<<<gg, 256, GEMM_H_SMEM>>>(xh, wh + 1 * WS, bk, nullptr, kh);
  gemm_h<<<gg, 256, GEMM_H_SMEM>>>(xh, wh + 2 * WS, bv, nullptr, vh);

  rope_h<<<(MROWS * NH * 64) / 256, 256>>>(qh, kh, cosb, sinb);

  attn_h<<<dim3(S_LEN / Q_ROWS, BATCH * NH), 128, A_SMEM>>>(qh, kh, vh, aoh);

  gemm_h<<<gg, 256, GEMM_H_SMEM>>>(aoh, wh + 3 * WS, nullptr, out, nullptr);
}